// round 6
// baseline (speedup 1.0000x reference)
#include <cuda_runtime.h>
#include <cuda_bf16.h>
#include <math.h>

// ---------------------------------------------------------------------------
// Problem constants
// ---------------------------------------------------------------------------
#define FEAT     128
#define FEAT3    384
#define NRBF     20
#define MAXNODES 20000

__device__ float g_h  [MAXNODES * FEAT];
__device__ float g_inv[MAXNODES * FEAT3];
__device__ int   g_nbrs_is64;   // 1 if nbrs buffer is int64, 0 if int32

// ---------------------------------------------------------------------------
// packed f32x2 helpers
// ---------------------------------------------------------------------------
__device__ __forceinline__ void fma2(unsigned long long &acc,
                                     unsigned long long a,
                                     unsigned long long b) {
    asm("fma.rn.f32x2 %0, %1, %2, %0;" : "+l"(acc) : "l"(a), "l"(b));
}
__device__ __forceinline__ unsigned long long mul2(unsigned long long a,
                                                   unsigned long long b) {
    unsigned long long r;
    asm("mul.rn.f32x2 %0, %1, %2;" : "=l"(r) : "l"(a), "l"(b));
    return r;
}
__device__ __forceinline__ unsigned long long add2(unsigned long long a,
                                                   unsigned long long b) {
    unsigned long long r;
    asm("add.rn.f32x2 %0, %1, %2;" : "=l"(r) : "l"(a), "l"(b));
    return r;
}
__device__ __forceinline__ unsigned long long fma2v(unsigned long long a,
                                                    unsigned long long b,
                                                    unsigned long long c) {
    unsigned long long r;
    asm("fma.rn.f32x2 %0, %1, %2, %3;" : "=l"(r) : "l"(a), "l"(b), "l"(c));
    return r;
}
__device__ __forceinline__ unsigned long long pack_dup(float x) {
    unsigned long long p;
    asm("mov.b64 %0, {%1, %1};" : "=l"(p) : "f"(x));
    return p;
}
__device__ __forceinline__ unsigned long long pack2(float x, float y) {
    unsigned long long p;
    asm("mov.b64 %0, {%1, %2};" : "=l"(p) : "f"(x), "f"(y));
    return p;
}
__device__ __forceinline__ void unpack2(unsigned long long p, float &x, float &y) {
    asm("mov.b64 {%0, %1}, %2;" : "=f"(x), "=f"(y) : "l"(p));
}

// ---------------------------------------------------------------------------
// nbrs dtype detector (int64 layout has all-zero odd u32 words)
// ---------------------------------------------------------------------------
__global__ void detect_nbrs_kernel(const unsigned int* __restrict__ p, int n_words)
{
    if (threadIdx.x == 0 && blockIdx.x == 0) {
        unsigned int acc = 0;
        int lim = n_words < 512 ? n_words : 512;
        for (int i = 1; i < lim; i += 2) acc |= p[i];
        g_nbrs_is64 = (acc == 0u) ? 1 : 0;
    }
}

// ---------------------------------------------------------------------------
// SGEMM: C[M,N] = A[M,K] @ B[K,N] + bias (optional silu)
// Occupancy-oriented tile: BM=64 BN=128 BK=16, 256 threads, TM=4 TN=8.
// acc = 16 u64 = 32 regs; 64-reg cap -> 4 CTAs/SM (50% occ).
// ---------------------------------------------------------------------------
#define BM 64
#define BN 128
#define BK 16

__global__ __launch_bounds__(256, 4) void sgemm_kernel(
    const float* __restrict__ A, const float* __restrict__ B,
    const float* __restrict__ bias, float* __restrict__ C,
    int M, int N, int K, int act)
{
    __shared__ __align__(16) float As[BK][BM + 4];
    __shared__ __align__(16) float Bs[BK][BN + 4];

    const int tid  = threadIdx.x;
    const int tx   = tid & 15;   // 16 col groups x 8 cols
    const int ty   = tid >> 4;   // 16 row groups x 4 rows
    const int row0 = blockIdx.x * BM;
    const int col0 = blockIdx.y * BN;

    unsigned long long acc[4][4];
    #pragma unroll
    for (int i = 0; i < 4; i++)
        #pragma unroll
        for (int j = 0; j < 4; j++) acc[i][j] = 0ull;

    for (int kk = 0; kk < K; kk += BK) {
        // A tile 64x16 = 256 float4; 1 per thread
        {
            int r  = tid >> 2;
            int kq = (tid & 3) * 4;
            float4 v = make_float4(0.f, 0.f, 0.f, 0.f);
            if (row0 + r < M)
                v = *(const float4*)&A[(size_t)(row0 + r) * K + kk + kq];
            As[kq + 0][r] = v.x; As[kq + 1][r] = v.y;
            As[kq + 2][r] = v.z; As[kq + 3][r] = v.w;
        }
        // B tile 16x128 = 512 float4; 2 per thread
        #pragma unroll
        for (int s = 0; s < 2; s++) {
            int f  = tid + s * 256;
            int kr = f >> 5;
            int nq = (f & 31) * 4;
            float4 v = *(const float4*)&B[(size_t)(kk + kr) * N + col0 + nq];
            *(float4*)&Bs[kr][nq] = v;
        }
        __syncthreads();

        #pragma unroll
        for (int k = 0; k < BK; k++) {
            float4 a = *(const float4*)&As[k][ty * 4];
            ulonglong2 b0 = *(const ulonglong2*)&Bs[k][tx * 8];
            ulonglong2 b1 = *(const ulonglong2*)&Bs[k][tx * 8 + 4];
            float av[4] = {a.x, a.y, a.z, a.w};
            unsigned long long bv[4] = {b0.x, b0.y, b1.x, b1.y};
            #pragma unroll
            for (int i = 0; i < 4; i++) {
                unsigned long long ad = pack_dup(av[i]);
                #pragma unroll
                for (int j = 0; j < 4; j++) fma2(acc[i][j], ad, bv[j]);
            }
        }
        __syncthreads();
    }

    #pragma unroll
    for (int i = 0; i < 4; i++) {
        int r = row0 + ty * 4 + i;
        if (r >= M) continue;
        #pragma unroll
        for (int j = 0; j < 4; j++) {
            int c = col0 + tx * 8 + j * 2;
            float x0, x1;
            unpack2(acc[i][j], x0, x1);
            x0 += bias[c];
            x1 += bias[c + 1];
            if (act) {
                x0 = x0 / (1.0f + expf(-x0));
                x1 = x1 / (1.0f + expf(-x1));
            }
            float2 o = make_float2(x0, x1);
            *(float2*)&C[(size_t)r * N + c] = o;
        }
    }
}

// ---------------------------------------------------------------------------
// Edge kernel (R4 structure + 5-CTA occupancy cap + f32x2 epilogue):
// out[e, c] = inv[j_e, c] * ((rbf_e @ Wr)[c]*env/d + br[c]*env)
// ---------------------------------------------------------------------------
#define ETILE 192

__global__ __launch_bounds__(192, 5) void edge_kernel(
    const float* __restrict__ dist,
    const int* __restrict__ nb,         // raw u32 words of nbrs
    const float* __restrict__ Wr,
    const float* __restrict__ br,
    const float* __restrict__ inv,
    float* __restrict__ out,
    int n_edges)
{
    __shared__ __align__(16) float  sm_s[ETILE][NRBF];  // sines
    __shared__ __align__(16) float4 sm_meta[ETILE];     // (k1, k2, j_bits, -)

    const int t  = threadIdx.x;
    const int c0 = t * 2;
    const int is64 = g_nbrs_is64;

    // weight pairs: wrA[m] = (Wr[2m][c0], Wr[2m+1][c0]); wrB for channel c0+1
    unsigned long long wrA[NRBF / 2];
    unsigned long long wrB[NRBF / 2];
    #pragma unroll
    for (int m = 0; m < NRBF / 2; m++) {
        float2 we = *(const float2*)&Wr[(2 * m)     * FEAT3 + c0];
        float2 wo = *(const float2*)&Wr[(2 * m + 1) * FEAT3 + c0];
        wrA[m] = pack2(we.x, wo.x);
        wrB[m] = pack2(we.y, wo.y);
    }
    const float2 brf = *(const float2*)&br[c0];
    const unsigned long long brp = pack2(brf.x, brf.y);

    const int base = blockIdx.x * ETILE;
    const int cnt  = min(ETILE, n_edges - base);

    // ---- phase A: one thread per edge --------------------------------------
    if (t < cnt) {
        const int e = base + t;
        const float d  = dist[e];
        const float th = d * 0.6283185307179586f;     // pi/5
        const float s1 = sinf(th);
        const float c1 = cosf(th);
        const float env = (d < 5.0f) ? 0.5f * (c1 + 1.0f) : 0.0f;
        const int   j   = is64 ? nb[4 * (long long)e + 2] : nb[2 * (long long)e + 1];
        sm_meta[t] = make_float4(env / d, env, __int_as_float(j), 0.0f);
        const float u = 2.0f * c1;
        float s[NRBF];
        float sp = 0.0f, sc = s1;
        #pragma unroll
        for (int n = 0; n < NRBF; n++) {
            s[n] = sc;
            float sn = fmaf(u, sc, -sp);
            sp = sc; sc = sn;
        }
        #pragma unroll
        for (int q = 0; q < NRBF / 4; q++)
            *(float4*)&sm_s[t][4 * q] =
                make_float4(s[4 * q], s[4 * q + 1], s[4 * q + 2], s[4 * q + 3]);
    }
    __syncthreads();

    // ---- phase B: sweep tile edges, pipelined gather ------------------------
    float4 meta = sm_meta[0];
    float2 ph   = *(const float2*)&inv[(size_t)__float_as_int(meta.z) * FEAT3 + c0];

    for (int i = 0; i < cnt; i++) {
        // prefetch next edge's meta + gathered phi (clamped; branchless)
        const int inext = (i + 1 < cnt) ? (i + 1) : i;
        float4 meta_n = sm_meta[inext];
        float2 ph_n   = *(const float2*)&inv[(size_t)__float_as_int(meta_n.z) * FEAT3 + c0];

        const ulonglong2* sr = (const ulonglong2*)sm_s[i];

        // 4 independent chains: {chan c0, c0+1} x {even-q, odd-q}
        unsigned long long a0e = 0ull, a0o = 0ull, a1e = 0ull, a1o = 0ull;
        #pragma unroll
        for (int q = 0; q < NRBF / 4; q++) {
            ulonglong2 sv = sr[q];   // LDS.128 broadcast: sines (4 per load)
            fma2(a0e, sv.x, wrA[2 * q]);
            fma2(a1e, sv.x, wrB[2 * q]);
            fma2(a0o, sv.y, wrA[2 * q + 1]);
            fma2(a1o, sv.y, wrB[2 * q + 1]);
        }
        // join chains per channel, then packed epilogue
        unsigned long long s0 = add2(a0e, a0o);   // (even,odd) sums of chan c0
        unsigned long long s1 = add2(a1e, a1o);   // chan c0+1
        float l0, h0, l1, h1;
        unpack2(s0, l0, h0);
        unpack2(s1, l1, h1);
        unsigned long long dpair = pack2(l0 + h0, l1 + h1);

        // w = d*k1 + br*k2 ; o = w*ph   (all packed f32x2)
        unsigned long long w = fma2v(dpair, pack_dup(meta.x),
                                     mul2(brp, pack_dup(meta.y)));
        unsigned long long php = pack2(ph.x, ph.y);
        unsigned long long o = mul2(w, php);
        *(unsigned long long*)&out[(size_t)(base + i) * FEAT3 + c0] = o;

        meta = meta_n;
        ph   = ph_n;
    }
}

// ---------------------------------------------------------------------------
// kernel_launch
// ---------------------------------------------------------------------------
extern "C" void kernel_launch(void* const* d_in, const int* in_sizes, int n_in,
                              void* d_out, int out_size)
{
    const float* s_j  = (const float*)d_in[0];
    const float* dist = (const float*)d_in[1];
    const int*   nb   = (const int*)  d_in[2];
    const float* W1   = (const float*)d_in[3];
    const float* b1   = (const float*)d_in[4];
    const float* W2   = (const float*)d_in[5];
    const float* b2   = (const float*)d_in[6];
    const float* Wr   = (const float*)d_in[7];
    const float* br   = (const float*)d_in[8];
    float*       out  = (float*)d_out;

    const int n_nodes = in_sizes[0] / FEAT;
    const int n_edges = in_sizes[1];

    float* hbuf;
    float* invbuf;
    cudaGetSymbolAddress((void**)&hbuf,   g_h);
    cudaGetSymbolAddress((void**)&invbuf, g_inv);

    detect_nbrs_kernel<<<1, 32>>>((const unsigned int*)nb, in_sizes[2]);

    // GEMM1: h = silu(s_j @ W1 + b1)
    {
        dim3 grid((n_nodes + BM - 1) / BM, FEAT / BN);
        sgemm_kernel<<<grid, 256>>>(s_j, W1, b1, hbuf,
                                    n_nodes, FEAT, FEAT, /*act=*/1);
    }
    // GEMM2: inv = h @ W2 + b2
    {
        dim3 grid((n_nodes + BM - 1) / BM, FEAT3 / BN);
        sgemm_kernel<<<grid, 256>>>(hbuf, W2, b2, invbuf,
                                    n_nodes, FEAT3, FEAT, /*act=*/0);
    }
    // Edge kernel
    {
        dim3 grid((n_edges + ETILE - 1) / ETILE);
        edge_kernel<<<grid, ETILE>>>(dist, nb, Wr, br, invbuf, out, n_edges);
    }
}

// round 7
// speedup vs baseline: 1.1884x; 1.1884x over previous
#include <cuda_runtime.h>
#include <cuda_bf16.h>
#include <math.h>

// ---------------------------------------------------------------------------
// Problem constants
// ---------------------------------------------------------------------------
#define FEAT     128
#define FEAT3    384
#define NRBF     20
#define MAXNODES 20000

__device__ float g_h  [MAXNODES * FEAT];
__device__ float g_inv[MAXNODES * FEAT3];
__device__ int   g_nbrs_is64;   // 1 if nbrs buffer is int64, 0 if int32

// ---------------------------------------------------------------------------
// packed f32x2 helpers
// ---------------------------------------------------------------------------
__device__ __forceinline__ void fma2(unsigned long long &acc,
                                     unsigned long long a,
                                     unsigned long long b) {
    asm("fma.rn.f32x2 %0, %1, %2, %0;" : "+l"(acc) : "l"(a), "l"(b));
}
__device__ __forceinline__ unsigned long long pack_dup(float x) {
    unsigned long long p;
    asm("mov.b64 %0, {%1, %1};" : "=l"(p) : "f"(x));
    return p;
}
__device__ __forceinline__ unsigned long long pack2(float x, float y) {
    unsigned long long p;
    asm("mov.b64 %0, {%1, %2};" : "=l"(p) : "f"(x), "f"(y));
    return p;
}
__device__ __forceinline__ void unpack2(unsigned long long p, float &x, float &y) {
    asm("mov.b64 {%0, %1}, %2;" : "=f"(x), "=f"(y) : "l"(p));
}

// ---------------------------------------------------------------------------
// nbrs dtype detector (int64 layout has all-zero odd u32 words)
// ---------------------------------------------------------------------------
__global__ void detect_nbrs_kernel(const unsigned int* __restrict__ p, int n_words)
{
    if (threadIdx.x == 0 && blockIdx.x == 0) {
        unsigned int acc = 0;
        int lim = n_words < 512 ? n_words : 512;
        for (int i = 1; i < lim; i += 2) acc |= p[i];
        g_nbrs_is64 = (acc == 0u) ? 1 : 0;
    }
}

// ---------------------------------------------------------------------------
// SGEMM (R3 version — measured ~98us for both GEMMs):
// C = A@B + bias (optional silu)
// BM=128 BN=128 BK=16, 256 threads, TM=8 TN=8, f32x2 accumulators
// ---------------------------------------------------------------------------
#define BM 128
#define BN 128
#define BK 16

__global__ __launch_bounds__(256) void sgemm_kernel(
    const float* __restrict__ A, const float* __restrict__ B,
    const float* __restrict__ bias, float* __restrict__ C,
    int M, int N, int K, int act)
{
    __shared__ __align__(16) float As[BK][BM + 4];
    __shared__ __align__(16) float Bs[BK][BN + 4];

    const int tid  = threadIdx.x;
    const int tx   = tid & 15;
    const int ty   = tid >> 4;
    const int row0 = blockIdx.x * BM;
    const int col0 = blockIdx.y * BN;

    unsigned long long acc[8][4];
    #pragma unroll
    for (int i = 0; i < 8; i++)
        #pragma unroll
        for (int j = 0; j < 4; j++) acc[i][j] = 0ull;

    for (int kk = 0; kk < K; kk += BK) {
        #pragma unroll
        for (int s = 0; s < 2; s++) {
            int f  = tid + s * 256;
            int r  = f >> 2;
            int kq = (f & 3) * 4;
            float4 v = make_float4(0.f, 0.f, 0.f, 0.f);
            if (row0 + r < M)
                v = *(const float4*)&A[(size_t)(row0 + r) * K + kk + kq];
            As[kq + 0][r] = v.x; As[kq + 1][r] = v.y;
            As[kq + 2][r] = v.z; As[kq + 3][r] = v.w;
        }
        #pragma unroll
        for (int s = 0; s < 2; s++) {
            int f  = tid + s * 256;
            int kr = f >> 5;
            int nq = (f & 31) * 4;
            float4 v = *(const float4*)&B[(size_t)(kk + kr) * N + col0 + nq];
            *(float4*)&Bs[kr][nq] = v;
        }
        __syncthreads();

        #pragma unroll
        for (int k = 0; k < BK; k++) {
            float4 a0 = *(const float4*)&As[k][ty * 8];
            float4 a1 = *(const float4*)&As[k][ty * 8 + 4];
            ulonglong2 b0 = *(const ulonglong2*)&Bs[k][tx * 8];
            ulonglong2 b1 = *(const ulonglong2*)&Bs[k][tx * 8 + 4];
            float av[8] = {a0.x, a0.y, a0.z, a0.w, a1.x, a1.y, a1.z, a1.w};
            unsigned long long bv[4] = {b0.x, b0.y, b1.x, b1.y};
            #pragma unroll
            for (int i = 0; i < 8; i++) {
                unsigned long long ad = pack_dup(av[i]);
                #pragma unroll
                for (int j = 0; j < 4; j++) fma2(acc[i][j], ad, bv[j]);
            }
        }
        __syncthreads();
    }

    #pragma unroll
    for (int i = 0; i < 8; i++) {
        int r = row0 + ty * 8 + i;
        if (r >= M) continue;
        #pragma unroll
        for (int j = 0; j < 4; j++) {
            int c = col0 + tx * 8 + j * 2;
            float x0, x1;
            unpack2(acc[i][j], x0, x1);
            x0 += bias[c];
            x1 += bias[c + 1];
            if (act) {
                x0 = x0 / (1.0f + expf(-x0));
                x1 = x1 / (1.0f + expf(-x1));
            }
            float2 o = make_float2(x0, x1);
            *(float2*)&C[(size_t)r * N + c] = o;
        }
    }
}

// ---------------------------------------------------------------------------
// Edge kernel (R4 version — measured 172.7us, 72 regs, natural occupancy):
// out[e, c] = inv[j_e, c] * ((rbf_e @ Wr)[c]*env/d + br[c]*env)
//  - two independent fma2 chains per channel (dep depth 5)
//  - inv[j] gather software-pipelined one edge ahead
//  - per-edge scalars packed in one float4
// ---------------------------------------------------------------------------
#define ETILE 192

__global__ __launch_bounds__(192) void edge_kernel(
    const float* __restrict__ dist,
    const int* __restrict__ nb,         // raw u32 words of nbrs
    const float* __restrict__ Wr,
    const float* __restrict__ br,
    const float* __restrict__ inv,
    float* __restrict__ out,
    int n_edges)
{
    __shared__ __align__(16) float  sm_s[ETILE][NRBF];  // sines
    __shared__ __align__(16) float4 sm_meta[ETILE];     // (k1, k2, j_bits, -)

    const int t  = threadIdx.x;
    const int c0 = t * 2;
    const int is64 = g_nbrs_is64;

    // weight pairs: wrA[m] = (Wr[2m][c0], Wr[2m+1][c0]); wrB for channel c0+1
    unsigned long long wrA[NRBF / 2];
    unsigned long long wrB[NRBF / 2];
    #pragma unroll
    for (int m = 0; m < NRBF / 2; m++) {
        float2 we = *(const float2*)&Wr[(2 * m)     * FEAT3 + c0];
        float2 wo = *(const float2*)&Wr[(2 * m + 1) * FEAT3 + c0];
        wrA[m] = pack2(we.x, wo.x);
        wrB[m] = pack2(we.y, wo.y);
    }
    const float2 brp = *(const float2*)&br[c0];

    const int base = blockIdx.x * ETILE;
    const int cnt  = min(ETILE, n_edges - base);

    // ---- phase A: one thread per edge --------------------------------------
    if (t < cnt) {
        const int e = base + t;
        const float d  = dist[e];
        const float th = d * 0.6283185307179586f;     // pi/5
        const float s1 = sinf(th);
        const float c1 = cosf(th);
        const float env = (d < 5.0f) ? 0.5f * (c1 + 1.0f) : 0.0f;
        const int   j   = is64 ? nb[4 * (long long)e + 2] : nb[2 * (long long)e + 1];
        sm_meta[t] = make_float4(env / d, env, __int_as_float(j), 0.0f);
        const float u = 2.0f * c1;
        float s[NRBF];
        float sp = 0.0f, sc = s1;
        #pragma unroll
        for (int n = 0; n < NRBF; n++) {
            s[n] = sc;
            float sn = fmaf(u, sc, -sp);
            sp = sc; sc = sn;
        }
        #pragma unroll
        for (int q = 0; q < NRBF / 4; q++)
            *(float4*)&sm_s[t][4 * q] =
                make_float4(s[4 * q], s[4 * q + 1], s[4 * q + 2], s[4 * q + 3]);
    }
    __syncthreads();

    // ---- phase B: sweep tile edges, pipelined gather ------------------------
    float4 meta = sm_meta[0];
    float2 ph   = *(const float2*)&inv[(size_t)__float_as_int(meta.z) * FEAT3 + c0];

    for (int i = 0; i < cnt; i++) {
        // prefetch next edge's meta + gathered phi (clamped; branchless)
        const int inext = (i + 1 < cnt) ? (i + 1) : i;
        float4 meta_n = sm_meta[inext];
        float2 ph_n   = *(const float2*)&inv[(size_t)__float_as_int(meta_n.z) * FEAT3 + c0];

        const ulonglong2* sr = (const ulonglong2*)sm_s[i];

        // 4 independent chains: {chan c0, c0+1} x {even-q, odd-q}
        unsigned long long a0e = 0ull, a0o = 0ull, a1e = 0ull, a1o = 0ull;
        #pragma unroll
        for (int q = 0; q < NRBF / 4; q++) {
            ulonglong2 sv = sr[q];   // LDS.128 broadcast: sines (4 per load)
            fma2(a0e, sv.x, wrA[2 * q]);
            fma2(a1e, sv.x, wrB[2 * q]);
            fma2(a0o, sv.y, wrA[2 * q + 1]);
            fma2(a1o, sv.y, wrB[2 * q + 1]);
        }
        float xe0, xo0, xe1, xo1, ye0, yo0, ye1, yo1;
        unpack2(a0e, xe0, xo0); unpack2(a0o, xe1, xo1);
        unpack2(a1e, ye0, yo0); unpack2(a1o, ye1, yo1);
        const float dx = (xe0 + xo0) + (xe1 + xo1);
        const float dy = (ye0 + yo0) + (ye1 + yo1);

        const float wx = fmaf(dx, meta.x, brp.x * meta.y);
        const float wy = fmaf(dy, meta.x, brp.y * meta.y);
        float2 o = make_float2(wx * ph.x, wy * ph.y);
        *(float2*)&out[(size_t)(base + i) * FEAT3 + c0] = o;

        meta = meta_n;
        ph   = ph_n;
    }
}

// ---------------------------------------------------------------------------
// kernel_launch
// ---------------------------------------------------------------------------
extern "C" void kernel_launch(void* const* d_in, const int* in_sizes, int n_in,
                              void* d_out, int out_size)
{
    const float* s_j  = (const float*)d_in[0];
    const float* dist = (const float*)d_in[1];
    const int*   nb   = (const int*)  d_in[2];
    const float* W1   = (const float*)d_in[3];
    const float* b1   = (const float*)d_in[4];
    const float* W2   = (const float*)d_in[5];
    const float* b2   = (const float*)d_in[6];
    const float* Wr   = (const float*)d_in[7];
    const float* br   = (const float*)d_in[8];
    float*       out  = (float*)d_out;

    const int n_nodes = in_sizes[0] / FEAT;
    const int n_edges = in_sizes[1];

    float* hbuf;
    float* invbuf;
    cudaGetSymbolAddress((void**)&hbuf,   g_h);
    cudaGetSymbolAddress((void**)&invbuf, g_inv);

    detect_nbrs_kernel<<<1, 32>>>((const unsigned int*)nb, in_sizes[2]);

    // GEMM1: h = silu(s_j @ W1 + b1)
    {
        dim3 grid((n_nodes + BM - 1) / BM, 1);
        sgemm_kernel<<<grid, 256>>>(s_j, W1, b1, hbuf,
                                    n_nodes, FEAT, FEAT, /*act=*/1);
    }
    // GEMM2: inv = h @ W2 + b2
    {
        dim3 grid((n_nodes + BM - 1) / BM, FEAT3 / BN);
        sgemm_kernel<<<grid, 256>>>(hbuf, W2, b2, invbuf,
                                    n_nodes, FEAT3, FEAT, /*act=*/0);
    }
    // Edge kernel
    {
        dim3 grid((n_edges + ETILE - 1) / ETILE);
        edge_kernel<<<grid, ETILE>>>(dist, nb, Wr, br, invbuf, out, n_edges);
    }
}